// round 4
// baseline (speedup 1.0000x reference)
#include <cuda_runtime.h>
#include <cuda_bf16.h>
#include <cstdint>

#define NTOK   4096
#define HDIM   4096
#define VOCAB  32000
#define M_TILE 128
#define N_TILE 128
#define KC     64
#define STAGES 4
#define KITERS (HDIM / KC)          // 64
#define NVT    (VOCAB / N_TILE)     // 250
#define A_STAGE (M_TILE * KC)       // 8192 B
#define B_STAGE (N_TILE * KC)       // 8192 B
#define STAGE_BYTES (A_STAGE + B_STAGE)   // 16384
#define SMEM_DYN (STAGES * STAGE_BYTES)   // 65536

#define SX 19.538461f    /* 127/6.5  */
#define SW 747.058824f   /* 127/0.17 */
#define INV_S (1.0f / (SX * SW))

// fragment-linear int8 buffers (uint4 for 16B alignment)
__device__ uint4 g_wq4[(size_t)VOCAB * HDIM / 16];   // [n_tile(4000)][k_tile(128)][256B]
__device__ uint4 g_xq4[(size_t)NTOK * HDIM / 16];    // [m_tile(256)][k_tile(128)][512B]
__device__ float g_partial[(size_t)NVT * NTOK];
__device__ float g_tgt[NTOK];
__device__ float g_bsum[32];
__device__ int   g_bcnt[32];

__device__ __forceinline__ uint32_t smem_u32(const void* p) {
    uint32_t a;
    asm("{ .reg .u64 t; cvta.to.shared.u64 t, %1; cvt.u32.u64 %0, t; }" : "=r"(a) : "l"(p));
    return a;
}
__device__ __forceinline__ void cp16(uint32_t dst, const void* src) {
    asm volatile("cp.async.cg.shared.global [%0], [%1], 16;" :: "r"(dst), "l"(src) : "memory");
}
__device__ __forceinline__ void lds128(uint32_t addr, uint32_t& r0, uint32_t& r1, uint32_t& r2, uint32_t& r3) {
    asm volatile("ld.shared.v4.b32 {%0,%1,%2,%3}, [%4];"
                 : "=r"(r0), "=r"(r1), "=r"(r2), "=r"(r3) : "r"(addr));
}
__device__ __forceinline__ void lds64(uint32_t addr, uint32_t& r0, uint32_t& r1) {
    asm volatile("ld.shared.v2.b32 {%0,%1}, [%2];" : "=r"(r0), "=r"(r1) : "r"(addr));
}
__device__ __forceinline__ void imma(int* d, const uint32_t* a, uint32_t b0, uint32_t b1) {
    asm volatile("mma.sync.aligned.m16n8k32.row.col.s32.s8.s8.s32 "
                 "{%0,%1,%2,%3}, {%4,%5,%6,%7}, {%8,%9}, {%0,%1,%2,%3};"
                 : "+r"(d[0]), "+r"(d[1]), "+r"(d[2]), "+r"(d[3])
                 : "r"(a[0]), "r"(a[1]), "r"(a[2]), "r"(a[3]), "r"(b0), "r"(b1));
}
__device__ __forceinline__ uint32_t q4(float4 v, float s) {
    int a = __float2int_rn(fminf(fmaxf(v.x * s, -127.f), 127.f));
    int b = __float2int_rn(fminf(fmaxf(v.y * s, -127.f), 127.f));
    int c = __float2int_rn(fminf(fmaxf(v.z * s, -127.f), 127.f));
    int d = __float2int_rn(fminf(fmaxf(v.w * s, -127.f), 127.f));
    return (a & 255) | ((b & 255) << 8) | ((c & 255) << 16) | ((d & 255) << 24);
}

// -------- quantize x into A-fragment-linear layout --------
// A tile 16x32: lane -> 16B: a0=(r,k..k+3) a1=(r+8,k) a2=(r,k+16) a3=(r+8,k+16)
__global__ void quant_x_kernel(const float* __restrict__ x) {
    const int t = blockIdx.x * 256 + threadIdx.x;   // 1,048,576
    const int lane = t & 31;
    const int wl = t >> 5;                          // m_tile*128 + k_tile
    const int mt = wl >> 7, kt = wl & 127;
    const int r = mt * 16 + (lane >> 2);
    const int k = kt * 32 + (lane & 3) * 4;
    const float* p0 = x + (size_t)r * HDIM + k;
    const float* p1 = p0 + 8 * HDIM;
    uint4 o;
    o.x = q4(*(const float4*)p0, SX);
    o.y = q4(*(const float4*)p1, SX);
    o.z = q4(*(const float4*)(p0 + 16), SX);
    o.w = q4(*(const float4*)(p1 + 16), SX);
    g_xq4[(size_t)wl * 32 + lane] = o;
}

// -------- quantize W into B-fragment-linear layout --------
// B tile 8x32 (col c, k): lane -> 8B: b0=(c,k..k+3) b1=(c,k+16)
__global__ void quant_w_kernel(const float* __restrict__ w) {
    const int t = blockIdx.x * 256 + threadIdx.x;   // 16,384,000
    const int lane = t & 31;
    const int wl = t >> 5;                          // n_tile*128 + k_tile
    const int nt = wl >> 7, kt = wl & 127;
    const int c = nt * 8 + (lane >> 2);
    const int k = kt * 32 + (lane & 3) * 4;
    const float* p = w + (size_t)c * HDIM + k;
    uint2 o;
    o.x = q4(*(const float4*)p, SW);
    o.y = q4(*(const float4*)(p + 16), SW);
    ((uint2*)g_wq4)[(size_t)wl * 32 + lane] = o;
}

// -------- int8 IMMA GEMM + fused exp-sum epilogue --------
__global__ void __launch_bounds__(256, 2)
fce_gemm_kernel(const float* __restrict__ bias) {
    extern __shared__ __align__(16) char smem[];
    __shared__ float redS[2][M_TILE];
    __shared__ float biasS[N_TILE];

    const uint32_t sb = smem_u32(smem);
    const int tid = threadIdx.x;
    const int lane = tid & 31;
    const int wid = tid >> 5;
    const int warp_m = wid & 3;            // 4 warps in M (32 rows each)
    const int warp_n = wid >> 2;           // 2 warps in N (64 cols each)
    const int m_blk = blockIdx.x;          // fast: share W tile in L2
    const int n_blk = blockIdx.y;

    const char* gA = (const char*)g_xq4 + (size_t)m_blk * 8 * 128 * 512;  // 8 m_tiles
    const char* gB = (const char*)g_wq4 + (size_t)n_blk * 16 * 128 * 256; // 16 n_tiles

    int acc[2][8][4];
#pragma unroll
    for (int i = 0; i < 2; i++)
#pragma unroll
        for (int j = 0; j < 8; j++)
#pragma unroll
            for (int k = 0; k < 4; k++) acc[i][j][k] = 0;

    // stage load: 1024 x 16B chunks (512 A + 512 B), 4 per thread
    auto load_stage = [&](int st, int it) {
        const uint32_t sA = sb + st * STAGE_BYTES;
#pragma unroll
        for (int j = 0; j < 4; j++) {
            const int cgl = tid + j * 256;
            if (cgl < 512) {
                // A chunk: mt = cgl>>6, kt = (cgl>>5)&1, i = cgl&31
                const int mt = cgl >> 6, kt = (cgl >> 5) & 1, ii = cgl & 31;
                cp16(sA + cgl * 16,
                     gA + ((size_t)mt * 128 + (size_t)it * 2 + kt) * 512 + ii * 16);
            } else {
                const int c2 = cgl - 512;
                const int nt = c2 >> 5, kt = (c2 >> 4) & 1, ii = c2 & 15;
                cp16(sA + A_STAGE + c2 * 16,
                     gB + ((size_t)nt * 128 + (size_t)it * 2 + kt) * 256 + ii * 16);
            }
        }
    };

#pragma unroll
    for (int s = 0; s < STAGES - 1; s++) {
        load_stage(s, s);
        asm volatile("cp.async.commit_group;" ::: "memory");
    }

    for (int it = 0; it < KITERS; ++it) {
        asm volatile("cp.async.wait_group 2;" ::: "memory");
        __syncthreads();
        const int pf = it + STAGES - 1;
        if (pf < KITERS) load_stage(pf & (STAGES - 1), pf);
        asm volatile("cp.async.commit_group;" ::: "memory");

        const int st = it & (STAGES - 1);
        const uint32_t sA = sb + st * STAGE_BYTES;
        const uint32_t sB = sA + A_STAGE;
#pragma unroll
        for (int ks = 0; ks < 2; ks++) {
            uint32_t a[2][4], b[8][2];
#pragma unroll
            for (int mi = 0; mi < 2; mi++)
                lds128(sA + (((warp_m * 2 + mi) * 2 + ks) * 512) + lane * 16,
                       a[mi][0], a[mi][1], a[mi][2], a[mi][3]);
#pragma unroll
            for (int j = 0; j < 8; j++)
                lds64(sB + (((warp_n * 8 + j) * 2 + ks) * 256) + lane * 8,
                      b[j][0], b[j][1]);
#pragma unroll
            for (int mi = 0; mi < 2; mi++)
#pragma unroll
                for (int j = 0; j < 8; j++)
                    imma(acc[mi][j], a[mi], b[j][0], b[j][1]);
        }
        __syncthreads();
    }

    // ---- epilogue: per-row sum of exp(logit*scale + bias) ----
    const int coly = n_blk * N_TILE;
    for (int i = tid; i < N_TILE; i += 256) biasS[i] = __ldg(&bias[coly + i]);
    __syncthreads();

    const int gid = lane >> 2, quad = lane & 3;
    float rs[2][2] = {{0.f, 0.f}, {0.f, 0.f}};
#pragma unroll
    for (int mi = 0; mi < 2; mi++)
#pragma unroll
        for (int j = 0; j < 8; j++) {
            const int col = warp_n * 64 + j * 8 + quad * 2;
            const float b0 = biasS[col], b1 = biasS[col + 1];
            rs[mi][0] += __expf((float)acc[mi][j][0] * INV_S + b0)
                       + __expf((float)acc[mi][j][1] * INV_S + b1);
            rs[mi][1] += __expf((float)acc[mi][j][2] * INV_S + b0)
                       + __expf((float)acc[mi][j][3] * INV_S + b1);
        }
#pragma unroll
    for (int off = 1; off <= 2; off <<= 1) {
#pragma unroll
        for (int mi = 0; mi < 2; mi++) {
            rs[mi][0] += __shfl_xor_sync(~0u, rs[mi][0], off);
            rs[mi][1] += __shfl_xor_sync(~0u, rs[mi][1], off);
        }
    }
    if (quad == 0) {
#pragma unroll
        for (int mi = 0; mi < 2; mi++) {
            redS[warp_n][warp_m * 32 + mi * 16 + gid] = rs[mi][0];
            redS[warp_n][warp_m * 32 + mi * 16 + 8 + gid] = rs[mi][1];
        }
    }
    __syncthreads();
    if (tid < M_TILE)
        g_partial[(size_t)n_blk * NTOK + m_blk * M_TILE + tid] = redS[0][tid] + redS[1][tid];
}

// -------- exact fp32 target logits --------
__device__ __forceinline__ bool tgt_is_i64(const int* p) {
    int bad = 0;
#pragma unroll
    for (int k = 0; k < 32; k++) {
        int v = p[2 * k + 1];
        bad |= (v != 0 && v != -1);
    }
    return !bad;
}
__global__ void tgt_kernel(const float* __restrict__ x, const float* __restrict__ w,
                           const int* __restrict__ tgt, const float* __restrict__ bias) {
    __shared__ float red[4];
    const int n = blockIdx.x, tid = threadIdx.x;
    const bool i64 = tgt_is_i64(tgt);
    const long long t = i64 ? ((const long long*)tgt)[n] : (long long)tgt[n];
    if (t < 0 || t >= VOCAB) { if (tid == 0) g_tgt[n] = 0.f; return; }
    const float4* xa = (const float4*)(x + (size_t)n * HDIM);
    const float4* wa = (const float4*)(w + (size_t)t * HDIM);
    float s = 0.f;
#pragma unroll
    for (int i = 0; i < 8; i++) {
        float4 a = xa[tid + 128 * i];
        float4 b = wa[tid + 128 * i];
        s += a.x * b.x + a.y * b.y + a.z * b.z + a.w * b.w;
    }
    for (int o = 16; o; o >>= 1) s += __shfl_xor_sync(~0u, s, o);
    if ((tid & 31) == 0) red[tid >> 5] = s;
    __syncthreads();
    if (tid == 0) g_tgt[n] = red[0] + red[1] + red[2] + red[3] + __ldg(&bias[t]);
}

// -------- deterministic reductions --------
__global__ void reduce1_kernel(const int* __restrict__ tgt) {
    const int tid = threadIdx.x;
    const int row = blockIdx.x * 128 + tid;
    const bool i64 = tgt_is_i64(tgt);
    const long long t = i64 ? ((const long long*)tgt)[row] : (long long)tgt[row];
    float rsum = 0.f;
    for (int c = 0; c < NVT; c++) rsum += g_partial[(size_t)c * NTOK + row];
    float nll = 0.f;
    int v = 0;
    if (t != -100LL) { nll = logf(rsum) - g_tgt[row]; v = 1; }
    for (int o = 16; o; o >>= 1) {
        nll += __shfl_xor_sync(~0u, nll, o);
        v   += __shfl_xor_sync(~0u, v, o);
    }
    __shared__ float fs[4];
    __shared__ int iv[4];
    if ((tid & 31) == 0) { fs[tid >> 5] = nll; iv[tid >> 5] = v; }
    __syncthreads();
    if (tid == 0) {
        g_bsum[blockIdx.x] = fs[0] + fs[1] + fs[2] + fs[3];
        g_bcnt[blockIdx.x] = iv[0] + iv[1] + iv[2] + iv[3];
    }
}
__global__ void reduce2_kernel(float* __restrict__ out) {
    const int tid = threadIdx.x;
    float s = g_bsum[tid];
    int c = g_bcnt[tid];
    for (int o = 16; o; o >>= 1) {
        s += __shfl_xor_sync(~0u, s, o);
        c += __shfl_xor_sync(~0u, c, o);
    }
    if (tid == 0) out[0] = s / (float)(c > 0 ? c : 1);
}

// -------- host --------
extern "C" void kernel_launch(void* const* d_in, const int* in_sizes, int n_in,
                              void* d_out, int out_size) {
    const float* w = nullptr;
    const float* x = nullptr;
    const float* bias = nullptr;
    const int* tgt = nullptr;
    for (int i = 0; i < n_in; i++) {
        switch (in_sizes[i]) {
            case 131072000: w = (const float*)d_in[i]; break;
            case 16777216:  x = (const float*)d_in[i]; break;
            case 4096:      tgt = (const int*)d_in[i]; break;
            case 32000:     bias = (const float*)d_in[i]; break;
            default: break;
        }
    }
    if (!w || !x || !tgt || !bias) return;

    cudaFuncSetAttribute(fce_gemm_kernel, cudaFuncAttributeMaxDynamicSharedMemorySize, SMEM_DYN);

    quant_x_kernel<<<NTOK * HDIM / 16 / 256, 256>>>(x);
    quant_w_kernel<<<VOCAB * (HDIM / 8) / 256, 256>>>(w);
    tgt_kernel<<<NTOK, 128>>>(x, w, tgt, bias);
    fce_gemm_kernel<<<dim3(NTOK / M_TILE, NVT), 256, SMEM_DYN>>>(bias);
    reduce1_kernel<<<32, 128>>>(tgt);
    reduce2_kernel<<<1, 32>>>((float*)d_out);
}

// round 7
// speedup vs baseline: 2.7249x; 2.7249x over previous
#include <cuda_runtime.h>
#include <cuda_bf16.h>
#include <cstdint>

#define NTOK   4096
#define HDIM   4096
#define VOCAB  32000
#define M_TILE 128
#define N_TILE 128
#define KC     64
#define STAGES 3
#define KITERS (HDIM / KC)          // 64
#define NVT    (VOCAB / N_TILE)     // 250
#define A_STAGE (M_TILE * KC * 2)   // 16384 B
#define B_STAGE (N_TILE * KC * 2)   // 16384 B
#define STAGE_BYTES (A_STAGE + B_STAGE)   // 32768
#define SMEM_DYN (STAGES * STAGE_BYTES)   // 98304

#define MT_ALL (NTOK / 16)          // 256 A m-tiles
#define NT_ALL (VOCAB / 8)          // 4000 B n-tiles
#define KT_ALL (HDIM / 16)          // 256 k-tiles

// fragment-linear bf16 buffers
__device__ uint4 g_xa[(size_t)MT_ALL * KT_ALL * 32];   // A tiles: 512B each, 33.5MB
__device__ uint2 g_wb[(size_t)NT_ALL * KT_ALL * 32];   // B tiles: 256B each, 262MB
__device__ float g_partial[(size_t)NVT * NTOK];
__device__ float g_tgt[NTOK];
__device__ float g_bsum[32];
__device__ int   g_bcnt[32];

__device__ __forceinline__ uint32_t smem_u32(const void* p) {
    uint32_t a;
    asm("{ .reg .u64 t; cvta.to.shared.u64 t, %1; cvt.u32.u64 %0, t; }" : "=r"(a) : "l"(p));
    return a;
}
__device__ __forceinline__ void cp16(uint32_t dst, const void* src) {
    asm volatile("cp.async.cg.shared.global [%0], [%1], 16;" :: "r"(dst), "l"(src) : "memory");
}
__device__ __forceinline__ void lds128(uint32_t addr, uint32_t& r0, uint32_t& r1, uint32_t& r2, uint32_t& r3) {
    asm volatile("ld.shared.v4.b32 {%0,%1,%2,%3}, [%4];"
                 : "=r"(r0), "=r"(r1), "=r"(r2), "=r"(r3) : "r"(addr));
}
__device__ __forceinline__ void lds64(uint32_t addr, uint32_t& r0, uint32_t& r1) {
    asm volatile("ld.shared.v2.b32 {%0,%1}, [%2];" : "=r"(r0), "=r"(r1) : "r"(addr));
}
__device__ __forceinline__ void mma16816(float* d, const uint32_t* a, uint32_t b0, uint32_t b1) {
    asm volatile("mma.sync.aligned.m16n8k16.row.col.f32.bf16.bf16.f32 "
                 "{%0,%1,%2,%3}, {%4,%5,%6,%7}, {%8,%9}, {%0,%1,%2,%3};"
                 : "+f"(d[0]), "+f"(d[1]), "+f"(d[2]), "+f"(d[3])
                 : "r"(a[0]), "r"(a[1]), "r"(a[2]), "r"(a[3]), "r"(b0), "r"(b1));
}
__device__ __forceinline__ uint32_t bfpair(const float* p) {
    __nv_bfloat162 h = __floats2bfloat162_rn(p[0], p[1]);
    return *reinterpret_cast<uint32_t*>(&h);
}

// -------- pack x into A-fragment-linear bf16 --------
// A tile (mt,kt) 16 rows x 16 k: lane l -> 16B: a0=(r, k),(r,k+1); a1=(r+8,k); a2=(r,k+8); a3=(r+8,k+8)
// r = mt*16 + (l>>2), k = kt*16 + 2*(l&3)
__global__ void conv_x_kernel(const float* __restrict__ x) {
    const int t = blockIdx.x * 256 + threadIdx.x;   // 2,097,152
    const int lane = t & 31;
    const int tile = t >> 5;
    const int mt = tile >> 8, kt = tile & 255;
    const int r = mt * 16 + (lane >> 2);
    const int k = kt * 16 + 2 * (lane & 3);
    const float* p0 = x + (size_t)r * HDIM + k;
    const float* p1 = p0 + 8 * HDIM;
    uint4 o;
    o.x = bfpair(p0);
    o.y = bfpair(p1);
    o.z = bfpair(p0 + 8);
    o.w = bfpair(p1 + 8);
    g_xa[(size_t)tile * 32 + lane] = o;
}

// -------- pack W into B-fragment-linear bf16 --------
// B tile (nt,kt) 8 cols x 16 k: lane l -> 8B: b0=(c, k),(c,k+1); b1=(c, k+8)
// c = nt*8 + (l>>2), k = kt*16 + 2*(l&3)
__global__ void conv_w_kernel(const float* __restrict__ w) {
    const int t = blockIdx.x * 256 + threadIdx.x;   // 32,768,000
    const int lane = t & 31;
    const int tile = t >> 5;
    const int nt = tile >> 8, kt = tile & 255;
    const int c = nt * 8 + (lane >> 2);
    const int k = kt * 16 + 2 * (lane & 3);
    const float* p = w + (size_t)c * HDIM + k;
    uint2 o;
    o.x = bfpair(p);
    o.y = bfpair(p + 8);
    g_wb[(size_t)tile * 32 + lane] = o;
}

// -------- bf16 HMMA GEMM + fused exp-sum epilogue --------
__global__ void __launch_bounds__(256, 2)
fce_gemm_kernel(const float* __restrict__ bias) {
    extern __shared__ __align__(16) char smem[];
    __shared__ float redS[2][M_TILE];
    __shared__ float biasS[N_TILE];

    const uint32_t sb = smem_u32(smem);
    const int tid = threadIdx.x;
    const int lane = tid & 31;
    const int wid = tid >> 5;
    const int warp_m = wid & 3;            // 4 warps in M (32 rows each)
    const int warp_n = wid >> 2;           // 2 warps in N (64 cols each)
    const int m_blk = blockIdx.x;          // fast-varying: W tile L2 reuse
    const int n_blk = blockIdx.y;

    const char* gA = (const char*)g_xa + (size_t)m_blk * 8 * KT_ALL * 512;
    const char* gB = (const char*)g_wb + (size_t)n_blk * 16 * KT_ALL * 256;

    float acc[2][8][4];
#pragma unroll
    for (int i = 0; i < 2; i++)
#pragma unroll
        for (int j = 0; j < 8; j++)
#pragma unroll
            for (int k = 0; k < 4; k++) acc[i][j][k] = 0.f;

    // stage: A = 8 m_tiles x 4 kt x 512B (1024 chunks), B = 16 n_tiles x 4 kt x 256B (1024 chunks)
    auto load_stage = [&](int st, int it) {
        const uint32_t sA = sb + st * STAGE_BYTES;
        const uint32_t sB = sA + A_STAGE;
#pragma unroll
        for (int j = 0; j < 8; j++) {
            const int cgl = tid + j * 256;
            if (cgl < 1024) {
                const int mtl = cgl >> 7, ktl = (cgl >> 5) & 3, li = cgl & 31;
                cp16(sA + cgl * 16,
                     gA + ((size_t)mtl * KT_ALL + it * 4 + ktl) * 512 + li * 16);
            } else {
                const int c2 = cgl - 1024;
                const int ntl = c2 >> 6, ktl = (c2 >> 4) & 3, ii = c2 & 15;
                cp16(sB + c2 * 16,
                     gB + ((size_t)ntl * KT_ALL + it * 4 + ktl) * 256 + ii * 16);
            }
        }
    };

#pragma unroll
    for (int s = 0; s < STAGES - 1; s++) {
        load_stage(s, s);
        asm volatile("cp.async.commit_group;" ::: "memory");
    }

    for (int it = 0; it < KITERS; ++it) {
        asm volatile("cp.async.wait_group 1;" ::: "memory");
        __syncthreads();
        const int pf = it + STAGES - 1;
        if (pf < KITERS) load_stage(pf % STAGES, pf);
        asm volatile("cp.async.commit_group;" ::: "memory");

        const int st = it % STAGES;
        const uint32_t sA = sb + st * STAGE_BYTES;
        const uint32_t sB = sA + A_STAGE;
#pragma unroll
        for (int ks = 0; ks < 4; ks++) {
            uint32_t a[2][4], b[8][2];
#pragma unroll
            for (int mi = 0; mi < 2; mi++)
                lds128(sA + ((warp_m * 2 + mi) * 4 + ks) * 512 + lane * 16,
                       a[mi][0], a[mi][1], a[mi][2], a[mi][3]);
#pragma unroll
            for (int j = 0; j < 8; j++)
                lds64(sB + ((warp_n * 8 + j) * 4 + ks) * 256 + lane * 8,
                      b[j][0], b[j][1]);
#pragma unroll
            for (int mi = 0; mi < 2; mi++)
#pragma unroll
                for (int j = 0; j < 8; j++)
                    mma16816(acc[mi][j], a[mi], b[j][0], b[j][1]);
        }
        __syncthreads();
    }

    // ---- epilogue: per-row sum of exp(logit + bias) ----
    const int coly = n_blk * N_TILE;
    for (int i = tid; i < N_TILE; i += 256) biasS[i] = __ldg(&bias[coly + i]);
    __syncthreads();

    const int gid = lane >> 2, quad = lane & 3;
    float rs[2][2] = {{0.f, 0.f}, {0.f, 0.f}};
#pragma unroll
    for (int mi = 0; mi < 2; mi++)
#pragma unroll
        for (int j = 0; j < 8; j++) {
            const int col = warp_n * 64 + j * 8 + quad * 2;
            const float b0 = biasS[col], b1 = biasS[col + 1];
            rs[mi][0] += __expf(acc[mi][j][0] + b0) + __expf(acc[mi][j][1] + b1);
            rs[mi][1] += __expf(acc[mi][j][2] + b0) + __expf(acc[mi][j][3] + b1);
        }
#pragma unroll
    for (int off = 1; off <= 2; off <<= 1) {
#pragma unroll
        for (int mi = 0; mi < 2; mi++) {
            rs[mi][0] += __shfl_xor_sync(~0u, rs[mi][0], off);
            rs[mi][1] += __shfl_xor_sync(~0u, rs[mi][1], off);
        }
    }
    if (quad == 0) {
#pragma unroll
        for (int mi = 0; mi < 2; mi++) {
            redS[warp_n][warp_m * 32 + mi * 16 + gid] = rs[mi][0];
            redS[warp_n][warp_m * 32 + mi * 16 + 8 + gid] = rs[mi][1];
        }
    }
    __syncthreads();
    if (tid < M_TILE)
        g_partial[(size_t)n_blk * NTOK + m_blk * M_TILE + tid] = redS[0][tid] + redS[1][tid];
}

// -------- exact fp32 target logits --------
__device__ __forceinline__ bool tgt_is_i64(const int* p) {
    int bad = 0;
#pragma unroll
    for (int k = 0; k < 32; k++) {
        int v = p[2 * k + 1];
        bad |= (v != 0 && v != -1);
    }
    return !bad;
}
__global__ void tgt_kernel(const float* __restrict__ x, const float* __restrict__ w,
                           const int* __restrict__ tgt, const float* __restrict__ bias) {
    __shared__ float red[4];
    const int n = blockIdx.x, tid = threadIdx.x;
    const bool i64 = tgt_is_i64(tgt);
    const long long t = i64 ? ((const long long*)tgt)[n] : (long long)tgt[n];
    if (t < 0 || t >= VOCAB) { if (tid == 0) g_tgt[n] = 0.f; return; }
    const float4* xa = (const float4*)(x + (size_t)n * HDIM);
    const float4* wa = (const float4*)(w + (size_t)t * HDIM);
    float s = 0.f;
#pragma unroll
    for (int i = 0; i < 8; i++) {
        float4 a = xa[tid + 128 * i];
        float4 b = wa[tid + 128 * i];
        s += a.x * b.x + a.y * b.y + a.z * b.z + a.w * b.w;
    }
    for (int o = 16; o; o >>= 1) s += __shfl_xor_sync(~0u, s, o);
    if ((tid & 31) == 0) red[tid >> 5] = s;
    __syncthreads();
    if (tid == 0) g_tgt[n] = red[0] + red[1] + red[2] + red[3] + __ldg(&bias[t]);
}

// -------- deterministic reductions --------
__global__ void reduce1_kernel(const int* __restrict__ tgt) {
    const int tid = threadIdx.x;
    const int row = blockIdx.x * 128 + tid;
    const bool i64 = tgt_is_i64(tgt);
    const long long t = i64 ? ((const long long*)tgt)[row] : (long long)tgt[row];
    float rsum = 0.f;
    for (int c = 0; c < NVT; c++) rsum += g_partial[(size_t)c * NTOK + row];
    float nll = 0.f;
    int v = 0;
    if (t != -100LL) { nll = logf(rsum) - g_tgt[row]; v = 1; }
    for (int o = 16; o; o >>= 1) {
        nll += __shfl_xor_sync(~0u, nll, o);
        v   += __shfl_xor_sync(~0u, v, o);
    }
    __shared__ float fs[4];
    __shared__ int iv[4];
    if ((tid & 31) == 0) { fs[tid >> 5] = nll; iv[tid >> 5] = v; }
    __syncthreads();
    if (tid == 0) {
        g_bsum[blockIdx.x] = fs[0] + fs[1] + fs[2] + fs[3];
        g_bcnt[blockIdx.x] = iv[0] + iv[1] + iv[2] + iv[3];
    }
}
__global__ void reduce2_kernel(float* __restrict__ out) {
    const int tid = threadIdx.x;
    float s = g_bsum[tid];
    int c = g_bcnt[tid];
    for (int o = 16; o; o >>= 1) {
        s += __shfl_xor_sync(~0u, s, o);
        c += __shfl_xor_sync(~0u, c, o);
    }
    if (tid == 0) out[0] = s / (float)(c > 0 ? c : 1);
}

// -------- host --------
extern "C" void kernel_launch(void* const* d_in, const int* in_sizes, int n_in,
                              void* d_out, int out_size) {
    const float* w = nullptr;
    const float* x = nullptr;
    const float* bias = nullptr;
    const int* tgt = nullptr;
    for (int i = 0; i < n_in; i++) {
        switch (in_sizes[i]) {
            case 131072000: w = (const float*)d_in[i]; break;
            case 16777216:  x = (const float*)d_in[i]; break;
            case 4096:      tgt = (const int*)d_in[i]; break;
            case 32000:     bias = (const float*)d_in[i]; break;
            default: break;
        }
    }
    if (!w || !x || !tgt || !bias) return;

    cudaFuncSetAttribute(fce_gemm_kernel, cudaFuncAttributeMaxDynamicSharedMemorySize, SMEM_DYN);

    conv_x_kernel<<<(MT_ALL * KT_ALL * 32) / 256, 256>>>(x);
    conv_w_kernel<<<(NT_ALL * KT_ALL * 32) / 256, 256>>>(w);
    tgt_kernel<<<NTOK, 128>>>(x, w, tgt, bias);
    fce_gemm_kernel<<<dim3(NTOK / M_TILE, NVT), 256, SMEM_DYN>>>(bias);
    reduce1_kernel<<<32, 128>>>(tgt);
    reduce2_kernel<<<1, 32>>>((float*)d_out);
}